// round 12
// baseline (speedup 1.0000x reference)
#include <cuda_runtime.h>

// OWA pooling: 3x3 window, stride 2, SAME pad (0 top/left, 1 bottom/right),
// sort window descending, dot with per-channel rank weights.
// inputs: (16,224,224,64) f32 NHWC ; kernel: (9,64) f32 ; out: (16,112,112,64) f32

#define B_  16
#define H_  224
#define W_  224
#define C_  64
#define OH_ 112
#define OW_ 112
#define OW_PER_WARP 14   // 112 / 8 warps

// Zero pad row for the bottom-pad pointer redirect (zero-initialized, never written).
__device__ float ZROW[W_ * C_];

// Descending compare-exchange, FMNMX form (alu pipe): 4 ops per float2
#define CE(i, j)                                          \
    {                                                     \
        float tx = fmaxf(v[i].x, v[j].x);                 \
        float ty = fmaxf(v[i].y, v[j].y);                 \
        v[j].x = fminf(v[i].x, v[j].x);                   \
        v[j].y = fminf(v[i].y, v[j].y);                   \
        v[i].x = tx;                                      \
        v[i].y = ty;                                      \
    }

// Descending compare-exchange, arithmetic form (fma pipe):
// max = 0.5*((a+b)+|a-b|), min = 0.5*((a+b)-|a-b|).
#define CEF(i, j)                                         \
    {                                                     \
        float sx = v[i].x + v[j].x;                       \
        float dx = v[i].x - v[j].x;                       \
        float sy = v[i].y + v[j].y;                       \
        float dy = v[i].y - v[j].y;                       \
        float mxx = sx + fabsf(dx);                       \
        float mnx = sx - fabsf(dx);                       \
        float mxy = sy + fabsf(dy);                       \
        float mny = sy - fabsf(dy);                       \
        v[i].x = 0.5f * mxx;                              \
        v[j].x = 0.5f * mnx;                              \
        v[i].y = 0.5f * mxy;                              \
        v[j].y = 0.5f * mny;                              \
    }

// The R4 body, templated on whether right-pad guarding is needed.
// GUARD=false (warps 0-6): provably col <= 198 < 224 -> zero predicates,
// every load is a bare LDG.64 with immediate offset after full unroll.
template <bool GUARD>
__device__ __forceinline__ void process_span(
    const float* __restrict__ base0,   // row r0   at channel c
    const float* __restrict__ base1,   // row r0+1 at channel c
    const float* __restrict__ base2,   // row r0+2 at channel c (or ZROW)
    const float2* __restrict__ wgt,    // 9 per-rank weights
    float* __restrict__ orow,          // output row at channel c
    int ow0)
{
    auto loadcol = [&](int col, float2* dst) {
        if (!GUARD || col < W_) {
            dst[0] = *reinterpret_cast<const float2*>(base0 + col * C_);
            dst[1] = *reinterpret_cast<const float2*>(base1 + col * C_);
            dst[2] = *reinterpret_cast<const float2*>(base2 + col * C_);
        } else {                        // right pad column (GUARD path only)
            dst[0] = make_float2(0.f, 0.f);
            dst[1] = make_float2(0.f, 0.f);
            dst[2] = make_float2(0.f, 0.f);
        }
    };

    float2 c0[3], c1[3], c2[3];
    loadcol(2 * ow0,     c0);
    loadcol(2 * ow0 + 1, c1);
    loadcol(2 * ow0 + 2, c2);

#pragma unroll
    for (int i = 0; i < OW_PER_WARP; ++i) {
        const int ow = ow0 + i;

        // Gather window into sort workspace (renamed away after unroll)
        float2 v[9];
        v[0] = c0[0]; v[1] = c0[1]; v[2] = c0[2];
        v[3] = c1[0]; v[4] = c1[1]; v[5] = c1[2];
        v[6] = c2[0]; v[7] = c2[1]; v[8] = c2[2];

        // Rotate and issue next columns' loads so the sort hides latency.
        c0[0] = c2[0]; c0[1] = c2[1]; c0[2] = c2[2];
        if (i + 1 < OW_PER_WARP) {
            loadcol(2 * ow + 3, c1);
            loadcol(2 * ow + 4, c2);
        }

        // Optimal 9-input sorting network: 25 CEs, depth 7 (descending).
        // 5 CEs on the fma pipe (CEF): analytic optimum of
        // max(issue_slots, alu_slots/0.5) over the CE/CEF split.
        CEF(0,3) CEF(1,7) CEF(2,5) CEF(4,8)
        CE(0,7) CE(2,4) CE(3,8) CEF(5,6)
        CE(0,2) CE(1,3) CE(4,5) CE(7,8)
        CE(1,4) CE(3,6) CE(5,7)
        CE(0,1) CE(2,4) CE(3,5) CE(6,8)
        CE(2,3) CE(4,5) CE(6,7)
        CE(1,2) CE(3,4) CE(5,6)

        // Rank-weighted sum (v[0] is the max, matching -sort(-p))
        float accx = v[0].x * wgt[0].x;
        float accy = v[0].y * wgt[0].y;
#pragma unroll
        for (int k = 1; k < 9; k++) {
            accx = fmaf(v[k].x, wgt[k].x, accx);
            accy = fmaf(v[k].y, wgt[k].y, accy);
        }

        *reinterpret_cast<float2*>(orow + ow * C_) = make_float2(accx, accy);
    }
}

__global__ __launch_bounds__(256, 3) void owa_pool_kernel(
    const float* __restrict__ in,   // (B,H,W,C)
    const float* __restrict__ kw,   // (9,C)
    float* __restrict__ out)        // (B,OH,OW,C)
{
    const int oh   = blockIdx.x;
    const int b    = blockIdx.y;
    const int warp = threadIdx.x >> 5;
    const int lane = threadIdx.x & 31;
    const int c    = lane * 2;          // this thread's channel pair

    // Per-rank weights for this channel pair (loop-invariant registers)
    float2 wgt[9];
#pragma unroll
    for (int k = 0; k < 9; k++)
        wgt[k] = *reinterpret_cast<const float2*>(kw + k * C_ + c);

    const int r0 = oh * 2;
    const float* base0 = in + ((b * H_ + r0) * W_) * C_ + c;
    const float* base1 = base0 + W_ * C_;
    // Bottom pad (oh == 111 only): redirect row-2 pointer to a zero row.
    // Removes the per-load r2ok predicate from every CTA.
    const float* base2 = (r0 + 2 < H_) ? (base0 + 2 * W_ * C_) : (ZROW + c);

    float* orow = out + ((b * OH_ + oh) * OW_) * C_ + c;
    const int ow0 = warp * OW_PER_WARP;

    // Warp-uniform branch: only warp 7 can touch the right-pad column
    // (warps 0-6: max col = 2*97+4 = 198 < 224). The fast path compiles
    // with zero bounds predicates.
    if (warp < 7) {
        process_span<false>(base0, base1, base2, wgt, orow, ow0);
    } else {
        process_span<true>(base0, base1, base2, wgt, orow, ow0);
    }
}

extern "C" void kernel_launch(void* const* d_in, const int* in_sizes, int n_in,
                              void* d_out, int out_size)
{
    const float* in = (const float*)d_in[0];   // (16,224,224,64)
    const float* kw = (const float*)d_in[1];   // (9,64)
    float* out = (float*)d_out;                // (16,112,112,64)

    dim3 grid(OH_, B_);
    dim3 block(256);
    owa_pool_kernel<<<grid, block>>>(in, kw, out);
}

// round 13
// speedup vs baseline: 1.0282x; 1.0282x over previous
#include <cuda_runtime.h>

// OWA pooling: 3x3 window, stride 2, SAME pad (0 top/left, 1 bottom/right),
// sort window descending, dot with per-channel rank weights.
// inputs: (16,224,224,64) f32 NHWC ; kernel: (9,64) f32 ; out: (16,112,112,64) f32
//
// R4 structure (best: 49.6us) + sm_103a packed f32x2 math:
//  - dot product: 9 packed FFMA2 instead of 18 scalar FFMA
//  - 8 of 25 compare-exchanges in packed "relu form" (2 alu + 3 fma slots)
// Total issue slots/iter ~130 vs ~171; alu pipe 84 slots vs ~80 -> wall bound
// drops from ~251 to ~200 cyc/warp-iter.

#define B_  16
#define H_  224
#define W_  224
#define C_  64
#define OH_ 112
#define OW_ 112
#define OW_PER_WARP 14   // 112 / 8 warps

// ---- packed f32x2 helpers (Blackwell-only PTX; ptxas elides the b64 movs
//      when it allocates the float2 halves as a register pair) ----
__device__ __forceinline__ float2 pfma(float2 a, float2 b, float2 c) {
    float2 r;
    asm("{\n\t"
        ".reg .b64 ra, rb, rc, rd;\n\t"
        "mov.b64 ra, {%2,%3};\n\t"
        "mov.b64 rb, {%4,%5};\n\t"
        "mov.b64 rc, {%6,%7};\n\t"
        "fma.rn.f32x2 rd, ra, rb, rc;\n\t"
        "mov.b64 {%0,%1}, rd;\n\t"
        "}"
        : "=f"(r.x), "=f"(r.y)
        : "f"(a.x), "f"(a.y), "f"(b.x), "f"(b.y), "f"(c.x), "f"(c.y));
    return r;
}
__device__ __forceinline__ float2 padd(float2 a, float2 b) {
    float2 r;
    asm("{\n\t"
        ".reg .b64 ra, rb, rd;\n\t"
        "mov.b64 ra, {%2,%3};\n\t"
        "mov.b64 rb, {%4,%5};\n\t"
        "add.rn.f32x2 rd, ra, rb;\n\t"
        "mov.b64 {%0,%1}, rd;\n\t"
        "}"
        : "=f"(r.x), "=f"(r.y)
        : "f"(a.x), "f"(a.y), "f"(b.x), "f"(b.y));
    return r;
}
__device__ __forceinline__ float2 pmul(float2 a, float2 b) {
    float2 r;
    asm("{\n\t"
        ".reg .b64 ra, rb, rd;\n\t"
        "mov.b64 ra, {%2,%3};\n\t"
        "mov.b64 rb, {%4,%5};\n\t"
        "mul.rn.f32x2 rd, ra, rb;\n\t"
        "mov.b64 {%0,%1}, rd;\n\t"
        "}"
        : "=f"(r.x), "=f"(r.y)
        : "f"(a.x), "f"(a.y), "f"(b.x), "f"(b.y));
    return r;
}

// Descending compare-exchange, FMNMX form (alu pipe): 4 slots per float2
#define CE(i, j)                                          \
    {                                                     \
        float tx = fmaxf(v[i].x, v[j].x);                 \
        float ty = fmaxf(v[i].y, v[j].y);                 \
        v[j].x = fminf(v[i].x, v[j].x);                   \
        v[j].y = fminf(v[i].y, v[j].y);                   \
        v[i].x = tx;                                      \
        v[i].y = ty;                                      \
    }

// Descending compare-exchange, packed relu form: 5 slots (2 alu + 3 fma).
// d = b - a; r = max(d, 0); max = a + r; min = b - r.  (<= 2 ulp)
#define CEP(i, j)                                         \
    {                                                     \
        float2 d = pfma(v[i], NEG1, v[j]);                \
        d.x = fmaxf(d.x, 0.f);                            \
        d.y = fmaxf(d.y, 0.f);                            \
        float2 mx = padd(v[i], d);                        \
        v[j] = pfma(d, NEG1, v[j]);                       \
        v[i] = mx;                                        \
    }

__global__ __launch_bounds__(256, 3) void owa_pool_kernel(
    const float* __restrict__ in,   // (B,H,W,C)
    const float* __restrict__ kw,   // (9,C)
    float* __restrict__ out)        // (B,OH,OW,C)
{
    const float2 NEG1 = make_float2(-1.f, -1.f);

    const int oh   = blockIdx.x;
    const int b    = blockIdx.y;
    const int warp = threadIdx.x >> 5;
    const int lane = threadIdx.x & 31;
    const int c    = lane * 2;          // this thread's channel pair

    // Per-rank weights for this channel pair (loop-invariant registers)
    float2 wgt[9];
#pragma unroll
    for (int k = 0; k < 9; k++)
        wgt[k] = *reinterpret_cast<const float2*>(kw + k * C_ + c);

    const int r0 = oh * 2;
    const bool r2ok = (r0 + 2 < H_);    // bottom pad row when oh == 111
    const float* base = in + ((b * H_ + r0) * W_) * C_ + c;

    // Load one input column (3 rows) of this channel pair; zeros for pad.
    auto loadcol = [&](int col, float2* dst) {
        if (col < W_) {
            dst[0] = *reinterpret_cast<const float2*>(base + col * C_);
            dst[1] = *reinterpret_cast<const float2*>(base + (W_ + col) * C_);
            dst[2] = r2ok
                   ? *reinterpret_cast<const float2*>(base + (2 * W_ + col) * C_)
                   : make_float2(0.f, 0.f);
        } else {                        // right pad column
            dst[0] = make_float2(0.f, 0.f);
            dst[1] = make_float2(0.f, 0.f);
            dst[2] = make_float2(0.f, 0.f);
        }
    };

    const int ow0 = warp * OW_PER_WARP;

    float2 c0[3], c1[3], c2[3];
    loadcol(2 * ow0,     c0);
    loadcol(2 * ow0 + 1, c1);
    loadcol(2 * ow0 + 2, c2);

    float* orow = out + ((b * OH_ + oh) * OW_) * C_ + c;

    // Fully unrolled: rotation/gather copies become register renames,
    // loop overhead disappears, ptxas schedules loads globally.
#pragma unroll
    for (int i = 0; i < OW_PER_WARP; ++i) {
        const int ow = ow0 + i;

        // Gather window into sort workspace (renamed away after unroll)
        float2 v[9];
        v[0] = c0[0]; v[1] = c0[1]; v[2] = c0[2];
        v[3] = c1[0]; v[4] = c1[1]; v[5] = c1[2];
        v[6] = c2[0]; v[7] = c2[1]; v[8] = c2[2];

        // Rotate and issue next columns' loads so the sort hides latency.
        c0[0] = c2[0]; c0[1] = c2[1]; c0[2] = c2[2];
        if (i + 1 < OW_PER_WARP) {
            loadcol(2 * ow + 3, c1);
            loadcol(2 * ow + 4, c2);
        }

        // Optimal 9-input sorting network: 25 CEs, depth 7 (descending).
        // Layers 1-2 (8 independent CEs) in packed relu form; rest FMNMX.
        CEP(0,3) CEP(1,7) CEP(2,5) CEP(4,8)
        CEP(0,7) CEP(2,4) CEP(3,8) CEP(5,6)
        CE(0,2) CE(1,3) CE(4,5) CE(7,8)
        CE(1,4) CE(3,6) CE(5,7)
        CE(0,1) CE(2,4) CE(3,5) CE(6,8)
        CE(2,3) CE(4,5) CE(6,7)
        CE(1,2) CE(3,4) CE(5,6)

        // Rank-weighted sum, fully packed: 9 FFMA2-class slots.
        float2 acc = pmul(v[0], wgt[0]);
#pragma unroll
        for (int k = 1; k < 9; k++)
            acc = pfma(v[k], wgt[k], acc);

        *reinterpret_cast<float2*>(orow + ow * C_) = acc;
    }
}

extern "C" void kernel_launch(void* const* d_in, const int* in_sizes, int n_in,
                              void* d_out, int out_size)
{
    const float* in = (const float*)d_in[0];   // (16,224,224,64)
    const float* kw = (const float*)d_in[1];   // (9,64)
    float* out = (float*)d_out;                // (16,112,112,64)

    dim3 grid(OH_, B_);
    dim3 block(256);
    owa_pool_kernel<<<grid, block>>>(in, kw, out);
}